// round 11
// baseline (speedup 1.0000x reference)
#include <cuda_runtime.h>
#include <cuda_fp16.h>

// MultiScaleDeformableAttention, GB300 sm_103a.
// B=4, Q=21760, NH=8, DH=32, NL=4, NP=4, S=21760
// levels (square): 128,64,32,16 ; element starts: 0,16384,20480,21504
//
// Kernel 1 (convert): value f32 [b,s,h,d] -> corner-pair-duplicated fp16
//   layout g_vdup[b,h,s][2*32] : for each cell s=(l,y,x) the 128B-ALIGNED
//   block holds { v[y,x][0..31], v[y,min(x+1,Wl-1)][0..31] } in fp16.
//   (2x duplication: 89MB, ~L2-scale.)
// Kernel 2 (main): one warp per (b,q,h). Per sample ONE LDG.64:
//   lanes 0-15 read the TOP cell block (one aligned 128B line), lanes 16-31
//   the BOTTOM block (+Wl*128B, compile-time per level). lane&8 = corner,
//   lane&7 = channel quad. Per sample: 2 shfl (cell offset, half2(Av,Bv)
//   weight) + 1 PRMT (row-select + duplicate) + 2 HFMA2 into PER-LEVEL fp16
//   accumulators; converted to f32 and summed once at the end (bounds fp16
//   rounding to 8 fma per accumulator). Final xor-8/xor-16 reduce, STG.128.

#define FULLMASK 0xffffffffu

constexpr int kQ = 21760;
constexpr int kS = 21760;

__device__ __align__(256) __half g_vdup[(size_t)4 * 8 * 21760 * 64]; // 89MB

// ---------------------------------------------------------------------------
// Pre-pass: build corner-pair-duplicated fp16 layout.
// One warp per (b,h,s): lanes 0-15 fetch row s (corner 0), lanes 16-31 row
// s2 = x+1 clamped (corner 1); each lane converts one float2 -> half2.
__global__ __launch_bounds__(256)
void convert_kernel(const float* __restrict__ value)
{
    const int warp = (blockIdx.x * 256 + threadIdx.x) >> 5;  // (b*8+h)*S + s? no:
    const int lane = threadIdx.x & 31;
    // warp index = ((b*8 + h) * kS + s) would be 22M warps; instead decode:
    const int bh = warp / kS;           // b*8 + h
    const int s  = warp - bh * kS;
    const int b  = bh >> 3;
    const int h  = bh & 7;

    // s -> level, x, clamped neighbor
    int l, base;
    if (s < 16384)      { l = 0; base = 0; }
    else if (s < 20480) { l = 1; base = 16384; }
    else if (s < 21504) { l = 2; base = 20480; }
    else                { l = 3; base = 21504; }
    const int Wl = 128 >> l;
    const int x  = (s - base) & (Wl - 1);
    const int s2 = (x < Wl - 1) ? s + 1 : s;     // clamped (junk corner, unused)

    const int corner = lane >> 4;
    const int c2     = lane & 15;
    const int srcs   = corner ? s2 : s;

    const float2 v = __ldg(reinterpret_cast<const float2*>(value)
                           + ((size_t)(b * kS + srcs) * 8 + h) * 16 + c2);
    const __half2 hv = __floats2half2_rn(v.x, v.y);

    *reinterpret_cast<__half2*>(g_vdup + ((size_t)bh * kS + s) * 64 + lane * 2) = hv;
}

// ---------------------------------------------------------------------------
__global__ __launch_bounds__(256)
void msda_kernel(const float* __restrict__ loc,
                 const float* __restrict__ attw,
                 float* __restrict__ out)
{
    const int warp = (blockIdx.x * 256 + threadIdx.x) >> 5;   // (b*Q+q)*8+h
    const int lane = threadIdx.x & 31;
    const int h  = warp & 7;
    const int bq = warp >> 3;
    const int b  = bq / kQ;

    // ---- precompute: lanes j and j+16 both do sample j; fold wx0 vs wx1 ----
    const int j = lane & 15;
    const float2 lc = __ldg(reinterpret_cast<const float2*>(loc) + (size_t)warp * 16 + j);
    const float  aw = __ldg(attw + (size_t)warp * 16 + j);

    const int   lvl = j >> 2;
    const int   Wl  = 128 >> lvl;
    const float Wf  = (float)Wl;

    const float x  = lc.x * Wf - 0.5f;
    const float y  = lc.y * Wf - 0.5f;
    const float xf = floorf(x);
    const float yf = floorf(y);
    const int   x0 = (int)xf;            // in [-1, Wl-1]
    const int   y0 = (int)yf;
    const float fx = x - xf;
    const float fy = y - yf;

    // Clamp base cell to [0, Wl-2]; remap weights so clamped-away corners get 0.
    float wx0 = 1.0f - fx, wx1 = fx;
    int   xb  = x0;
    if (x0 < 0)      { xb = 0;      wx0 = fx;   wx1 = 0.0f; }
    if (x0 > Wl - 2) { xb = Wl - 2; wx0 = 0.0f; wx1 = 1.0f - fx; }
    float wy0 = 1.0f - fy, wy1 = fy;
    int   yb  = y0;
    if (y0 < 0)      { yb = 0;      wy0 = fy;   wy1 = 0.0f; }
    if (y0 > Wl - 2) { yb = Wl - 2; wy0 = 0.0f; wy1 = 1.0f - fy; }

    const float xw = (lane & 16) ? wx1 : wx0;     // low half: LEFT corner
    const float Av = wy0 * aw * xw;               // top-row corner weight
    const float Bv = wy1 * aw * xw;               // bottom-row corner weight

    const __half2 wh = __floats2half2_rn(Av, Bv); // low=Av(top), high=Bv(bottom)
    unsigned wab_u;
    asm("mov.b32 %0, %1;" : "=r"(wab_u) : "r"(*reinterpret_cast<const unsigned*>(&wh)));

    // In-level cell byte offset (cell block = 128B).
    const int offv = (yb * Wl + xb) << 7;

    // ---- main-loop lane roles ----------------------------------------------
    // row = lane>>4 ; corner = (lane>>3)&1 ; channel quad = lane&7
    const int csrc   = (lane & 8) << 1;             // corner -> +16 shfl source
    const unsigned prmctl = (lane & 16) ? 0x3232u : 0x1010u;  // dup own row half
    const int rowoff0 = (lane >> 4) << 14;          // row * 128 * 128B (level 0)

    const char* plane = reinterpret_cast<const char*>(
        g_vdup + (size_t)(b * 8 + h) * kS * 64) + (lane & 15) * 8;

    const int LSb[4] = {0, 16384 * 128, 20480 * 128, 21504 * 128};

    __half2 acc0[4], acc1[4];
#pragma unroll
    for (int l = 0; l < 4; ++l) {
        acc0[l] = __half2half2(__ushort_as_half(0));
        acc1[l] = __half2half2(__ushort_as_half(0));
    }

#pragma unroll
    for (int l = 0; l < 4; ++l) {
        const char* base_l = plane + LSb[l] + (rowoff0 >> l);
#pragma unroll
        for (int p = 0; p < 4; ++p) {
            const int s   = l * 4 + p;
            const int src = s | csrc;

            const int      o  = __shfl_sync(FULLMASK, offv,  src);
            const unsigned ww = __shfl_sync(FULLMASK, wab_u, src);
            const unsigned wd = __byte_perm(ww, 0, prmctl);
            const __half2  w2 = *reinterpret_cast<const __half2*>(&wd);

            const uint2 v = __ldg(reinterpret_cast<const uint2*>(base_l + o));
            acc0[l] = __hfma2(w2, *reinterpret_cast<const __half2*>(&v.x), acc0[l]);
            acc1[l] = __hfma2(w2, *reinterpret_cast<const __half2*>(&v.y), acc1[l]);
        }
    }

    // ---- f32 combine of per-level fp16 partials -----------------------------
    float r0 = 0.f, r1 = 0.f, r2 = 0.f, r3 = 0.f;
#pragma unroll
    for (int l = 0; l < 4; ++l) {
        const float2 f0 = __half22float2(acc0[l]);
        const float2 f1 = __half22float2(acc1[l]);
        r0 += f0.x; r1 += f0.y; r2 += f1.x; r3 += f1.y;
    }

    // ---- reduce across corner (xor 8) and row (xor 16) groups --------------
#pragma unroll
    for (int m = 8; m <= 16; m <<= 1) {
        r0 += __shfl_xor_sync(FULLMASK, r0, m);
        r1 += __shfl_xor_sync(FULLMASK, r1, m);
        r2 += __shfl_xor_sync(FULLMASK, r2, m);
        r3 += __shfl_xor_sync(FULLMASK, r3, m);
    }

    if (lane < 8) {
        float4 o4 = make_float4(r0, r1, r2, r3);
        *reinterpret_cast<float4*>(out + (size_t)bq * 256 + h * 32 + lane * 4) = o4;
    }
}

extern "C" void kernel_launch(void* const* d_in, const int* in_sizes, int n_in,
                              void* d_out, int out_size)
{
    const float* value = (const float*)d_in[0];
    const float* loc   = (const float*)d_in[3];
    const float* attw  = (const float*)d_in[4];
    float* out = (float*)d_out;

    // Convert: 4*8*21760 = 696320 warps -> 87040 blocks.
    convert_kernel<<<696320 / 8, 256>>>(value);
    // Main: 4*21760*8 = 696320 warps -> 87040 blocks.
    msda_kernel<<<696320 / 8, 256>>>(loc, attw, out);
}

// round 12
// speedup vs baseline: 1.0011x; 1.0011x over previous
#include <cuda_runtime.h>
#include <cuda_fp16.h>

// MultiScaleDeformableAttention, GB300 sm_103a.
// B=4, Q=21760, NH=8, DH=32, NL=4, NP=4, S=21760
// levels (square): 128,64,32,16 ; element starts: 0,16384,20480,21504
//
// Kernel 1 (convert): value f32 [b,s,h,d] -> corner-pair-duplicated fp16
//   layout g_vdup[b,h,s][2*32] : for each cell s=(l,y,x) the 128B-ALIGNED
//   block holds { v[y,x][0..31], v[y,min(x+1,Wl-1)][0..31] } in fp16.
//   (2x duplication: 89MB, ~L2-scale.)
// Kernel 2 (main): one warp per (b,q,h). Per sample ONE LDG.64:
//   lanes 0-15 read the TOP cell block (one aligned 128B line), lanes 16-31
//   the BOTTOM block (+Wl*128B, compile-time per level). lane&8 = corner,
//   lane&7 = channel quad. Per sample: 2 shfl (cell offset, half2(Av,Bv)
//   weight) + 1 PRMT (row-select + duplicate) + 2 HFMA2 into PER-LEVEL fp16
//   accumulators; converted to f32 and summed once at the end (bounds fp16
//   rounding to 8 fma per accumulator). Final xor-8/xor-16 reduce, STG.128.

#define FULLMASK 0xffffffffu

constexpr int kQ = 21760;
constexpr int kS = 21760;

__device__ __align__(256) __half g_vdup[(size_t)4 * 8 * 21760 * 64]; // 89MB

// ---------------------------------------------------------------------------
// Pre-pass: build corner-pair-duplicated fp16 layout.
// One warp per (b,h,s): lanes 0-15 fetch row s (corner 0), lanes 16-31 row
// s2 = x+1 clamped (corner 1); each lane converts one float2 -> half2.
__global__ __launch_bounds__(256)
void convert_kernel(const float* __restrict__ value)
{
    const int warp = (blockIdx.x * 256 + threadIdx.x) >> 5;  // (b*8+h)*S + s? no:
    const int lane = threadIdx.x & 31;
    // warp index = ((b*8 + h) * kS + s) would be 22M warps; instead decode:
    const int bh = warp / kS;           // b*8 + h
    const int s  = warp - bh * kS;
    const int b  = bh >> 3;
    const int h  = bh & 7;

    // s -> level, x, clamped neighbor
    int l, base;
    if (s < 16384)      { l = 0; base = 0; }
    else if (s < 20480) { l = 1; base = 16384; }
    else if (s < 21504) { l = 2; base = 20480; }
    else                { l = 3; base = 21504; }
    const int Wl = 128 >> l;
    const int x  = (s - base) & (Wl - 1);
    const int s2 = (x < Wl - 1) ? s + 1 : s;     // clamped (junk corner, unused)

    const int corner = lane >> 4;
    const int c2     = lane & 15;
    const int srcs   = corner ? s2 : s;

    const float2 v = __ldg(reinterpret_cast<const float2*>(value)
                           + ((size_t)(b * kS + srcs) * 8 + h) * 16 + c2);
    const __half2 hv = __floats2half2_rn(v.x, v.y);

    *reinterpret_cast<__half2*>(g_vdup + ((size_t)bh * kS + s) * 64 + lane * 2) = hv;
}

// ---------------------------------------------------------------------------
__global__ __launch_bounds__(256)
void msda_kernel(const float* __restrict__ loc,
                 const float* __restrict__ attw,
                 float* __restrict__ out)
{
    const int warp = (blockIdx.x * 256 + threadIdx.x) >> 5;   // (b*Q+q)*8+h
    const int lane = threadIdx.x & 31;
    const int h  = warp & 7;
    const int bq = warp >> 3;
    const int b  = bq / kQ;

    // ---- precompute: lanes j and j+16 both do sample j; fold wx0 vs wx1 ----
    const int j = lane & 15;
    const float2 lc = __ldg(reinterpret_cast<const float2*>(loc) + (size_t)warp * 16 + j);
    const float  aw = __ldg(attw + (size_t)warp * 16 + j);

    const int   lvl = j >> 2;
    const int   Wl  = 128 >> lvl;
    const float Wf  = (float)Wl;

    const float x  = lc.x * Wf - 0.5f;
    const float y  = lc.y * Wf - 0.5f;
    const float xf = floorf(x);
    const float yf = floorf(y);
    const int   x0 = (int)xf;            // in [-1, Wl-1]
    const int   y0 = (int)yf;
    const float fx = x - xf;
    const float fy = y - yf;

    // Clamp base cell to [0, Wl-2]; remap weights so clamped-away corners get 0.
    float wx0 = 1.0f - fx, wx1 = fx;
    int   xb  = x0;
    if (x0 < 0)      { xb = 0;      wx0 = fx;   wx1 = 0.0f; }
    if (x0 > Wl - 2) { xb = Wl - 2; wx0 = 0.0f; wx1 = 1.0f - fx; }
    float wy0 = 1.0f - fy, wy1 = fy;
    int   yb  = y0;
    if (y0 < 0)      { yb = 0;      wy0 = fy;   wy1 = 0.0f; }
    if (y0 > Wl - 2) { yb = Wl - 2; wy0 = 0.0f; wy1 = 1.0f - fy; }

    const float xw = (lane & 16) ? wx1 : wx0;     // low half: LEFT corner
    const float Av = wy0 * aw * xw;               // top-row corner weight
    const float Bv = wy1 * aw * xw;               // bottom-row corner weight

    const __half2 wh = __floats2half2_rn(Av, Bv); // low=Av(top), high=Bv(bottom)
    unsigned wab_u;
    asm("mov.b32 %0, %1;" : "=r"(wab_u) : "r"(*reinterpret_cast<const unsigned*>(&wh)));

    // In-level cell byte offset (cell block = 128B).
    const int offv = (yb * Wl + xb) << 7;

    // ---- main-loop lane roles ----------------------------------------------
    // row = lane>>4 ; corner = (lane>>3)&1 ; channel quad = lane&7
    const int csrc   = (lane & 8) << 1;             // corner -> +16 shfl source
    const unsigned prmctl = (lane & 16) ? 0x3232u : 0x1010u;  // dup own row half
    const int rowoff0 = (lane >> 4) << 14;          // row * 128 * 128B (level 0)

    const char* plane = reinterpret_cast<const char*>(
        g_vdup + (size_t)(b * 8 + h) * kS * 64) + (lane & 15) * 8;

    const int LSb[4] = {0, 16384 * 128, 20480 * 128, 21504 * 128};

    __half2 acc0[4], acc1[4];
#pragma unroll
    for (int l = 0; l < 4; ++l) {
        acc0[l] = __half2half2(__ushort_as_half(0));
        acc1[l] = __half2half2(__ushort_as_half(0));
    }

#pragma unroll
    for (int l = 0; l < 4; ++l) {
        const char* base_l = plane + LSb[l] + (rowoff0 >> l);
#pragma unroll
        for (int p = 0; p < 4; ++p) {
            const int s   = l * 4 + p;
            const int src = s | csrc;

            const int      o  = __shfl_sync(FULLMASK, offv,  src);
            const unsigned ww = __shfl_sync(FULLMASK, wab_u, src);
            const unsigned wd = __byte_perm(ww, 0, prmctl);
            const __half2  w2 = *reinterpret_cast<const __half2*>(&wd);

            const uint2 v = __ldg(reinterpret_cast<const uint2*>(base_l + o));
            acc0[l] = __hfma2(w2, *reinterpret_cast<const __half2*>(&v.x), acc0[l]);
            acc1[l] = __hfma2(w2, *reinterpret_cast<const __half2*>(&v.y), acc1[l]);
        }
    }

    // ---- f32 combine of per-level fp16 partials -----------------------------
    float r0 = 0.f, r1 = 0.f, r2 = 0.f, r3 = 0.f;
#pragma unroll
    for (int l = 0; l < 4; ++l) {
        const float2 f0 = __half22float2(acc0[l]);
        const float2 f1 = __half22float2(acc1[l]);
        r0 += f0.x; r1 += f0.y; r2 += f1.x; r3 += f1.y;
    }

    // ---- reduce across corner (xor 8) and row (xor 16) groups --------------
#pragma unroll
    for (int m = 8; m <= 16; m <<= 1) {
        r0 += __shfl_xor_sync(FULLMASK, r0, m);
        r1 += __shfl_xor_sync(FULLMASK, r1, m);
        r2 += __shfl_xor_sync(FULLMASK, r2, m);
        r3 += __shfl_xor_sync(FULLMASK, r3, m);
    }

    if (lane < 8) {
        float4 o4 = make_float4(r0, r1, r2, r3);
        *reinterpret_cast<float4*>(out + (size_t)bq * 256 + h * 32 + lane * 4) = o4;
    }
}

extern "C" void kernel_launch(void* const* d_in, const int* in_sizes, int n_in,
                              void* d_out, int out_size)
{
    const float* value = (const float*)d_in[0];
    const float* loc   = (const float*)d_in[3];
    const float* attw  = (const float*)d_in[4];
    float* out = (float*)d_out;

    // Convert: 4*8*21760 = 696320 warps -> 87040 blocks.
    convert_kernel<<<696320 / 8, 256>>>(value);
    // Main: 4*21760*8 = 696320 warps -> 87040 blocks.
    msda_kernel<<<696320 / 8, 256>>>(loc, attw, out);
}

// round 13
// speedup vs baseline: 1.0016x; 1.0004x over previous
#include <cuda_runtime.h>
#include <cuda_fp16.h>

// MultiScaleDeformableAttention, GB300 sm_103a.
// B=4, Q=21760, NH=8, DH=32, NL=4, NP=4, S=21760
// levels (square): 128,64,32,16 ; element starts: 0,16384,20480,21504
//
// Kernel 1 (convert): value f32 [b,s,h,d] -> corner-pair-duplicated fp16
//   layout g_vdup[b,h,s][2*32] : for each cell s=(l,y,x) the 128B-ALIGNED
//   block holds { v[y,x][0..31], v[y,min(x+1,Wl-1)][0..31] } in fp16.
//   (2x duplication: 89MB, ~L2-scale.)
// Kernel 2 (main): one warp per (b,q,h). Per sample ONE LDG.64:
//   lanes 0-15 read the TOP cell block (one aligned 128B line), lanes 16-31
//   the BOTTOM block (+Wl*128B, compile-time per level). lane&8 = corner,
//   lane&7 = channel quad. Per sample: 2 shfl (cell offset, half2(Av,Bv)
//   weight) + 1 PRMT (row-select + duplicate) + 2 HFMA2 into PER-LEVEL fp16
//   accumulators; converted to f32 and summed once at the end (bounds fp16
//   rounding to 8 fma per accumulator). Final xor-8/xor-16 reduce, STG.128.

#define FULLMASK 0xffffffffu

constexpr int kQ = 21760;
constexpr int kS = 21760;

__device__ __align__(256) __half g_vdup[(size_t)4 * 8 * 21760 * 64]; // 89MB

// ---------------------------------------------------------------------------
// Pre-pass: build corner-pair-duplicated fp16 layout.
// One warp per (b,h,s): lanes 0-15 fetch row s (corner 0), lanes 16-31 row
// s2 = x+1 clamped (corner 1); each lane converts one float2 -> half2.
__global__ __launch_bounds__(256)
void convert_kernel(const float* __restrict__ value)
{
    const int warp = (blockIdx.x * 256 + threadIdx.x) >> 5;  // (b*8+h)*S + s? no:
    const int lane = threadIdx.x & 31;
    // warp index = ((b*8 + h) * kS + s) would be 22M warps; instead decode:
    const int bh = warp / kS;           // b*8 + h
    const int s  = warp - bh * kS;
    const int b  = bh >> 3;
    const int h  = bh & 7;

    // s -> level, x, clamped neighbor
    int l, base;
    if (s < 16384)      { l = 0; base = 0; }
    else if (s < 20480) { l = 1; base = 16384; }
    else if (s < 21504) { l = 2; base = 20480; }
    else                { l = 3; base = 21504; }
    const int Wl = 128 >> l;
    const int x  = (s - base) & (Wl - 1);
    const int s2 = (x < Wl - 1) ? s + 1 : s;     // clamped (junk corner, unused)

    const int corner = lane >> 4;
    const int c2     = lane & 15;
    const int srcs   = corner ? s2 : s;

    const float2 v = __ldg(reinterpret_cast<const float2*>(value)
                           + ((size_t)(b * kS + srcs) * 8 + h) * 16 + c2);
    const __half2 hv = __floats2half2_rn(v.x, v.y);

    *reinterpret_cast<__half2*>(g_vdup + ((size_t)bh * kS + s) * 64 + lane * 2) = hv;
}

// ---------------------------------------------------------------------------
__global__ __launch_bounds__(256)
void msda_kernel(const float* __restrict__ loc,
                 const float* __restrict__ attw,
                 float* __restrict__ out)
{
    const int warp = (blockIdx.x * 256 + threadIdx.x) >> 5;   // (b*Q+q)*8+h
    const int lane = threadIdx.x & 31;
    const int h  = warp & 7;
    const int bq = warp >> 3;
    const int b  = bq / kQ;

    // ---- precompute: lanes j and j+16 both do sample j; fold wx0 vs wx1 ----
    const int j = lane & 15;
    const float2 lc = __ldg(reinterpret_cast<const float2*>(loc) + (size_t)warp * 16 + j);
    const float  aw = __ldg(attw + (size_t)warp * 16 + j);

    const int   lvl = j >> 2;
    const int   Wl  = 128 >> lvl;
    const float Wf  = (float)Wl;

    const float x  = lc.x * Wf - 0.5f;
    const float y  = lc.y * Wf - 0.5f;
    const float xf = floorf(x);
    const float yf = floorf(y);
    const int   x0 = (int)xf;            // in [-1, Wl-1]
    const int   y0 = (int)yf;
    const float fx = x - xf;
    const float fy = y - yf;

    // Clamp base cell to [0, Wl-2]; remap weights so clamped-away corners get 0.
    float wx0 = 1.0f - fx, wx1 = fx;
    int   xb  = x0;
    if (x0 < 0)      { xb = 0;      wx0 = fx;   wx1 = 0.0f; }
    if (x0 > Wl - 2) { xb = Wl - 2; wx0 = 0.0f; wx1 = 1.0f - fx; }
    float wy0 = 1.0f - fy, wy1 = fy;
    int   yb  = y0;
    if (y0 < 0)      { yb = 0;      wy0 = fy;   wy1 = 0.0f; }
    if (y0 > Wl - 2) { yb = Wl - 2; wy0 = 0.0f; wy1 = 1.0f - fy; }

    const float xw = (lane & 16) ? wx1 : wx0;     // low half: LEFT corner
    const float Av = wy0 * aw * xw;               // top-row corner weight
    const float Bv = wy1 * aw * xw;               // bottom-row corner weight

    const __half2 wh = __floats2half2_rn(Av, Bv); // low=Av(top), high=Bv(bottom)
    unsigned wab_u;
    asm("mov.b32 %0, %1;" : "=r"(wab_u) : "r"(*reinterpret_cast<const unsigned*>(&wh)));

    // In-level cell byte offset (cell block = 128B).
    const int offv = (yb * Wl + xb) << 7;

    // ---- main-loop lane roles ----------------------------------------------
    // row = lane>>4 ; corner = (lane>>3)&1 ; channel quad = lane&7
    const int csrc   = (lane & 8) << 1;             // corner -> +16 shfl source
    const unsigned prmctl = (lane & 16) ? 0x3232u : 0x1010u;  // dup own row half
    const int rowoff0 = (lane >> 4) << 14;          // row * 128 * 128B (level 0)

    const char* plane = reinterpret_cast<const char*>(
        g_vdup + (size_t)(b * 8 + h) * kS * 64) + (lane & 15) * 8;

    const int LSb[4] = {0, 16384 * 128, 20480 * 128, 21504 * 128};

    __half2 acc0[4], acc1[4];
#pragma unroll
    for (int l = 0; l < 4; ++l) {
        acc0[l] = __half2half2(__ushort_as_half(0));
        acc1[l] = __half2half2(__ushort_as_half(0));
    }

#pragma unroll
    for (int l = 0; l < 4; ++l) {
        const char* base_l = plane + LSb[l] + (rowoff0 >> l);
#pragma unroll
        for (int p = 0; p < 4; ++p) {
            const int s   = l * 4 + p;
            const int src = s | csrc;

            const int      o  = __shfl_sync(FULLMASK, offv,  src);
            const unsigned ww = __shfl_sync(FULLMASK, wab_u, src);
            const unsigned wd = __byte_perm(ww, 0, prmctl);
            const __half2  w2 = *reinterpret_cast<const __half2*>(&wd);

            const uint2 v = __ldg(reinterpret_cast<const uint2*>(base_l + o));
            acc0[l] = __hfma2(w2, *reinterpret_cast<const __half2*>(&v.x), acc0[l]);
            acc1[l] = __hfma2(w2, *reinterpret_cast<const __half2*>(&v.y), acc1[l]);
        }
    }

    // ---- f32 combine of per-level fp16 partials -----------------------------
    float r0 = 0.f, r1 = 0.f, r2 = 0.f, r3 = 0.f;
#pragma unroll
    for (int l = 0; l < 4; ++l) {
        const float2 f0 = __half22float2(acc0[l]);
        const float2 f1 = __half22float2(acc1[l]);
        r0 += f0.x; r1 += f0.y; r2 += f1.x; r3 += f1.y;
    }

    // ---- reduce across corner (xor 8) and row (xor 16) groups --------------
#pragma unroll
    for (int m = 8; m <= 16; m <<= 1) {
        r0 += __shfl_xor_sync(FULLMASK, r0, m);
        r1 += __shfl_xor_sync(FULLMASK, r1, m);
        r2 += __shfl_xor_sync(FULLMASK, r2, m);
        r3 += __shfl_xor_sync(FULLMASK, r3, m);
    }

    if (lane < 8) {
        float4 o4 = make_float4(r0, r1, r2, r3);
        *reinterpret_cast<float4*>(out + (size_t)bq * 256 + h * 32 + lane * 4) = o4;
    }
}

extern "C" void kernel_launch(void* const* d_in, const int* in_sizes, int n_in,
                              void* d_out, int out_size)
{
    const float* value = (const float*)d_in[0];
    const float* loc   = (const float*)d_in[3];
    const float* attw  = (const float*)d_in[4];
    float* out = (float*)d_out;

    // Convert: 4*8*21760 = 696320 warps -> 87040 blocks.
    convert_kernel<<<696320 / 8, 256>>>(value);
    // Main: 4*21760*8 = 696320 warps -> 87040 blocks.
    msda_kernel<<<696320 / 8, 256>>>(loc, attw, out);
}

// round 14
// speedup vs baseline: 1.2405x; 1.2386x over previous
#include <cuda_runtime.h>
#include <cuda_fp16.h>

// MultiScaleDeformableAttention, GB300 sm_103a.
// B=4, Q=21760, NH=8, DH=32, NL=4, NP=4, S=21760
// levels (square): 128,64,32,16 ; element starts: 0,16384,20480,21504
//
// Layout (g_vdup, 89MB): per (b,h,cell s) one 128B block of 32 interleaved
// corner pairs: { v_s[ch], v_{s+1}[ch] } fp16 for ch=0..31. Cells with
// x==Wl-1 hold junk in the second slot (never read: base cell xb<=Wl-2).
//
// Kernel 1 (convert): warp per (b,h,strip of 8 cells): 9 coalesced 128B f32
//   slice loads (read-once), 8x cvt f32x2->f16x2 builds interleaved pairs,
//   8 single-line 128B stores.
// Kernel 2 (main): warp per (b,q,h). Lane = (row bit4, parity bit3, quad 0-2).
//   One LDG.128 per TWO samples (512B = 2 samples x 2 rows x 128B, 4 lines).
//   Per iter: 1 IADD(src) + 2 SHFL (offset & half2 weight, same source lane,
//   keyed by (sample,row)) + 1 IADD + LDG.128 + 4 HFMA2. Weight half2
//   (w_c0,w_c1) multiplies value half2 (v_c0,v_c1) directly - no PRMT.
//   fp16 accumulators split levels{0,1}/{2,3} (4 roundings each); f32 corner
//   sum + xor8/xor16 reduce; lanes 0-7 STG.128.

#define FULLMASK 0xffffffffu

constexpr int kQ = 21760;
constexpr int kS = 21760;

__device__ __align__(256) __half g_vdup[(size_t)4 * 8 * 21760 * 64]; // 89MB

// ---------------------------------------------------------------------------
// Convert: warp per (b,h,strip8). Read rows s0..s0+8 once, emit 8 blocks.
__global__ __launch_bounds__(256)
void convert_kernel(const float* __restrict__ value)
{
    const int warp = (blockIdx.x * 256 + threadIdx.x) >> 5;   // [0, 87040)
    const int lane = threadIdx.x & 31;

    const int bh    = warp / 2720;            // b*8 + h
    const int strip = warp - bh * 2720;
    const int b     = bh >> 3;
    const int h     = bh & 7;
    const int s0    = strip * 8;

    float f[9];
#pragma unroll
    for (int r = 0; r < 9; ++r) {
        const int s = (s0 + r < kS) ? s0 + r : kS - 1;        // clamp last strip
        f[r] = __ldg(value + ((size_t)(b * kS + s) * 8 + h) * 32 + lane);
    }

    __half* dst = g_vdup + ((size_t)bh * kS + s0) * 64 + lane * 2;
#pragma unroll
    for (int k = 0; k < 8; ++k) {
        const __half2 hv = __floats2half2_rn(f[k], f[k + 1]); // (c0, c1)
        *reinterpret_cast<__half2*>(dst + (size_t)k * 64) = hv;
    }
}

// ---------------------------------------------------------------------------
__global__ __launch_bounds__(256)
void msda_kernel(const float* __restrict__ loc,
                 const float* __restrict__ attw,
                 float* __restrict__ out)
{
    const int warp = (blockIdx.x * 256 + threadIdx.x) >> 5;   // (b*Q+q)*8+h
    const int lane = threadIdx.x & 31;
    const int h  = warp & 7;
    const int bq = warp >> 3;
    const int b  = bq / kQ;

    // ---- precompute: lane j = sample j top row, lane j+16 = bottom row -----
    const int j = lane & 15;
    const float2 lc = __ldg(reinterpret_cast<const float2*>(loc) + (size_t)warp * 16 + j);
    const float  aw = __ldg(attw + (size_t)warp * 16 + j);

    const int   lvl = j >> 2;
    const int   Wl  = 128 >> lvl;
    const float Wf  = (float)Wl;

    const float x  = lc.x * Wf - 0.5f;
    const float y  = lc.y * Wf - 0.5f;
    const float xf = floorf(x);
    const float yf = floorf(y);
    const int   x0 = (int)xf;            // in [-1, Wl-1]
    const int   y0 = (int)yf;
    const float fx = x - xf;
    const float fy = y - yf;

    // Clamp base cell to [0, Wl-2]; remap weights so clamped-away corners get 0.
    float wx0 = 1.0f - fx, wx1 = fx;
    int   xb  = x0;
    if (x0 < 0)      { xb = 0;      wx0 = fx;   wx1 = 0.0f; }
    if (x0 > Wl - 2) { xb = Wl - 2; wx0 = 0.0f; wx1 = 1.0f - fx; }
    float wy0 = 1.0f - fy, wy1 = fy;
    int   yb  = y0;
    if (y0 < 0)      { yb = 0;      wy0 = fy;   wy1 = 0.0f; }
    if (y0 > Wl - 2) { yb = Wl - 2; wy0 = 0.0f; wy1 = 1.0f - fy; }

    const int   row = lane >> 4;                  // 0 = top, 1 = bottom
    const float wyr = row ? wy1 : wy0;
    const __half2 wh = __floats2half2_rn(wyr * aw * wx0, wyr * aw * wx1);
    const unsigned Wu = *reinterpret_cast<const unsigned*>(&wh);

    // Byte offset of this (sample,row)'s 128B block within the level.
    const int offv = ((yb + row) * Wl + xb) << 7;

    // ---- main-loop lane roles ----------------------------------------------
    // row = lane>>4, parity = (lane>>3)&1, channel quad = lane&7
    const int laneterm = ((lane >> 3) & 1) + (lane & 16);   // shfl src term

    const char* plane = reinterpret_cast<const char*>(
        g_vdup + (size_t)(b * 8 + h) * kS * 64) + (lane & 7) * 16;

    const int LSb[4] = {0, 16384 * 128, 20480 * 128, 21504 * 128};

    __half2 accA[4], accB[4];
#pragma unroll
    for (int i = 0; i < 4; ++i) {
        accA[i] = __half2half2(__ushort_as_half(0));
        accB[i] = __half2half2(__ushort_as_half(0));
    }

#pragma unroll
    for (int l = 0; l < 4; ++l) {
#pragma unroll
        for (int p2 = 0; p2 < 2; ++p2) {
            const int k   = l * 2 + p2;           // iter; samples 2k, 2k+1
            const int src = 2 * k + laneterm;

            const int      o  = __shfl_sync(FULLMASK, offv, src);
            const unsigned wu = __shfl_sync(FULLMASK, Wu,   src);
            const __half2  w2 = *reinterpret_cast<const __half2*>(&wu);

            const uint4 v = __ldg(reinterpret_cast<const uint4*>(plane + LSb[l] + o));
            __half2* acc = (l < 2) ? accA : accB;
            acc[0] = __hfma2(w2, *reinterpret_cast<const __half2*>(&v.x), acc[0]);
            acc[1] = __hfma2(w2, *reinterpret_cast<const __half2*>(&v.y), acc[1]);
            acc[2] = __hfma2(w2, *reinterpret_cast<const __half2*>(&v.z), acc[2]);
            acc[3] = __hfma2(w2, *reinterpret_cast<const __half2*>(&v.w), acc[3]);
        }
    }

    // ---- combine level sets, corner pairs; reduce parity(8) + row(16) -------
    float r[4];
#pragma unroll
    for (int i = 0; i < 4; ++i) {
        const float2 fA = __half22float2(accA[i]);
        const float2 fB = __half22float2(accB[i]);
        r[i] = (fA.x + fB.x) + (fA.y + fB.y);     // corner0 + corner1
    }

#pragma unroll
    for (int m = 8; m <= 16; m <<= 1) {
        r[0] += __shfl_xor_sync(FULLMASK, r[0], m);
        r[1] += __shfl_xor_sync(FULLMASK, r[1], m);
        r[2] += __shfl_xor_sync(FULLMASK, r[2], m);
        r[3] += __shfl_xor_sync(FULLMASK, r[3], m);
    }

    if (lane < 8) {
        // lane q holds channels 4q..4q+3 ; 8 lanes x float4 = 128B coalesced
        float4 o4 = make_float4(r[0], r[1], r[2], r[3]);
        *reinterpret_cast<float4*>(out + (size_t)bq * 256 + h * 32 + lane * 4) = o4;
    }
}

extern "C" void kernel_launch(void* const* d_in, const int* in_sizes, int n_in,
                              void* d_out, int out_size)
{
    const float* value = (const float*)d_in[0];
    const float* loc   = (const float*)d_in[3];
    const float* attw  = (const float*)d_in[4];
    float* out = (float*)d_out;

    // Convert: 4*8*(21760/8) = 87040 warps -> 10880 blocks.
    convert_kernel<<<10880, 256>>>(value);
    // Main: 4*21760*8 = 696320 warps -> 87040 blocks.
    msda_kernel<<<87040, 256>>>(loc, attw, out);
}

// round 15
// speedup vs baseline: 1.2942x; 1.0433x over previous
#include <cuda_runtime.h>
#include <cuda_fp16.h>

// MultiScaleDeformableAttention, GB300 sm_103a.
// B=4, Q=21760, NH=8, DH=32, NL=4, NP=4, S=21760
// levels (square): 128,64,32,16 ; element starts: 0,16384,20480,21504
//
// Layout (g_vdup, 89MB): per (b,h,cell s) one 128B block of 32 interleaved
// corner pairs { v_s[ch], v_{s+1}[ch] } fp16. x==Wl-1 second slot is junk
// (never read: base cell xb<=Wl-2).
//
// Kernel 1 (convert): warp per (b,h,strip of 8 cells): 9 coalesced f32 slice
//   loads (read-once), 8x cvt f32x2->f16x2, 8 single-line stores.
// Kernel 2 (main): warp per (b,q,h). Lane=(row bit4, parity bit3, quad 0-2).
//   One LDG.128 per TWO samples. SOFTWARE-PIPELINED: all 16 shfls (8 offsets
//   + 8 packed half2 weights) hoisted, then loads issued in two batches of 4
//   LDG.128 with the HFMA2 consumption deferred past the next batch's issue
//   (explicit MLP ~4-8, hides L2/DRAM latency). fp16 accumulators split
//   levels{0,1}/{2,3}; f32 corner sum; xor8/xor16 reduce; lanes 0-7 STG.128.

#define FULLMASK 0xffffffffu

constexpr int kQ = 21760;
constexpr int kS = 21760;

__device__ __align__(256) __half g_vdup[(size_t)4 * 8 * 21760 * 64]; // 89MB

// ---------------------------------------------------------------------------
__global__ __launch_bounds__(256)
void convert_kernel(const float* __restrict__ value)
{
    const int warp = (blockIdx.x * 256 + threadIdx.x) >> 5;   // [0, 87040)
    const int lane = threadIdx.x & 31;

    const int bh    = warp / 2720;            // b*8 + h
    const int strip = warp - bh * 2720;
    const int b     = bh >> 3;
    const int h     = bh & 7;
    const int s0    = strip * 8;

    float f[9];
#pragma unroll
    for (int r = 0; r < 9; ++r) {
        const int s = (s0 + r < kS) ? s0 + r : kS - 1;        // clamp last strip
        f[r] = __ldg(value + ((size_t)(b * kS + s) * 8 + h) * 32 + lane);
    }

    __half* dst = g_vdup + ((size_t)bh * kS + s0) * 64 + lane * 2;
#pragma unroll
    for (int k = 0; k < 8; ++k) {
        const __half2 hv = __floats2half2_rn(f[k], f[k + 1]); // (c0, c1)
        *reinterpret_cast<__half2*>(dst + (size_t)k * 64) = hv;
    }
}

// ---------------------------------------------------------------------------
__global__ __launch_bounds__(256)
void msda_kernel(const float* __restrict__ loc,
                 const float* __restrict__ attw,
                 float* __restrict__ out)
{
    const int warp = (blockIdx.x * 256 + threadIdx.x) >> 5;   // (b*Q+q)*8+h
    const int lane = threadIdx.x & 31;
    const int h  = warp & 7;
    const int bq = warp >> 3;
    const int b  = bq / kQ;

    // ---- precompute: lane j = sample j top row, lane j+16 = bottom row -----
    const int j = lane & 15;
    const float2 lc = __ldg(reinterpret_cast<const float2*>(loc) + (size_t)warp * 16 + j);
    const float  aw = __ldg(attw + (size_t)warp * 16 + j);

    const int   lvl = j >> 2;
    const int   Wl  = 128 >> lvl;
    const float Wf  = (float)Wl;

    const float x  = lc.x * Wf - 0.5f;
    const float y  = lc.y * Wf - 0.5f;
    const float xf = floorf(x);
    const float yf = floorf(y);
    const int   x0 = (int)xf;            // in [-1, Wl-1]
    const int   y0 = (int)yf;
    const float fx = x - xf;
    const float fy = y - yf;

    // Clamp base cell to [0, Wl-2]; remap weights so clamped-away corners get 0.
    float wx0 = 1.0f - fx, wx1 = fx;
    int   xb  = x0;
    if (x0 < 0)      { xb = 0;      wx0 = fx;   wx1 = 0.0f; }
    if (x0 > Wl - 2) { xb = Wl - 2; wx0 = 0.0f; wx1 = 1.0f - fx; }
    float wy0 = 1.0f - fy, wy1 = fy;
    int   yb  = y0;
    if (y0 < 0)      { yb = 0;      wy0 = fy;   wy1 = 0.0f; }
    if (y0 > Wl - 2) { yb = Wl - 2; wy0 = 0.0f; wy1 = 1.0f - fy; }

    const int   row = lane >> 4;                  // 0 = top, 1 = bottom
    const float wyr = row ? wy1 : wy0;
    const __half2 wh = __floats2half2_rn(wyr * aw * wx0, wyr * aw * wx1);
    const unsigned Wu = *reinterpret_cast<const unsigned*>(&wh);

    // Byte offset of this (sample,row)'s 128B block within the level.
    const int offv = ((yb + row) * Wl + xb) << 7;

    // ---- main-loop lane roles ----------------------------------------------
    const int laneterm = ((lane >> 3) & 1) + (lane & 16);   // shfl src term

    const char* plane = reinterpret_cast<const char*>(
        g_vdup + (size_t)(b * 8 + h) * kS * 64) + (lane & 7) * 16;

    const int LSb[4] = {0, 16384 * 128, 20480 * 128, 21504 * 128};

    // ---- phase 1: all parameter shfls (independent) -------------------------
    int      o[8];
    unsigned wu[8];
#pragma unroll
    for (int k = 0; k < 8; ++k) {
        const int src = 2 * k + laneterm;
        o[k]  = __shfl_sync(FULLMASK, offv, src);
        wu[k] = __shfl_sync(FULLMASK, Wu,   src);
    }

    __half2 accA[4], accB[4];
#pragma unroll
    for (int i = 0; i < 4; ++i) {
        accA[i] = __half2half2(__ushort_as_half(0));
        accB[i] = __half2half2(__ushort_as_half(0));
    }

    // ---- phase 2: batched loads (MLP), deferred consumption -----------------
    uint4 v0[4], v1[4];
#pragma unroll
    for (int k = 0; k < 4; ++k)      // batch 0: levels 0,1 (samples 0..7)
        v0[k] = __ldg(reinterpret_cast<const uint4*>(plane + LSb[k >> 1] + o[k]));
#pragma unroll
    for (int k = 0; k < 4; ++k)      // batch 1: levels 2,3 (samples 8..15)
        v1[k] = __ldg(reinterpret_cast<const uint4*>(plane + LSb[2 + (k >> 1)] + o[4 + k]));

#pragma unroll
    for (int k = 0; k < 4; ++k) {
        const __half2 w2 = *reinterpret_cast<const __half2*>(&wu[k]);
        accA[0] = __hfma2(w2, *reinterpret_cast<const __half2*>(&v0[k].x), accA[0]);
        accA[1] = __hfma2(w2, *reinterpret_cast<const __half2*>(&v0[k].y), accA[1]);
        accA[2] = __hfma2(w2, *reinterpret_cast<const __half2*>(&v0[k].z), accA[2]);
        accA[3] = __hfma2(w2, *reinterpret_cast<const __half2*>(&v0[k].w), accA[3]);
    }
#pragma unroll
    for (int k = 0; k < 4; ++k) {
        const __half2 w2 = *reinterpret_cast<const __half2*>(&wu[4 + k]);
        accB[0] = __hfma2(w2, *reinterpret_cast<const __half2*>(&v1[k].x), accB[0]);
        accB[1] = __hfma2(w2, *reinterpret_cast<const __half2*>(&v1[k].y), accB[1]);
        accB[2] = __hfma2(w2, *reinterpret_cast<const __half2*>(&v1[k].z), accB[2]);
        accB[3] = __hfma2(w2, *reinterpret_cast<const __half2*>(&v1[k].w), accB[3]);
    }

    // ---- combine level sets, corner pairs; reduce parity(8) + row(16) -------
    float r[4];
#pragma unroll
    for (int i = 0; i < 4; ++i) {
        const float2 fA = __half22float2(accA[i]);
        const float2 fB = __half22float2(accB[i]);
        r[i] = (fA.x + fB.x) + (fA.y + fB.y);     // corner0 + corner1
    }

#pragma unroll
    for (int m = 8; m <= 16; m <<= 1) {
        r[0] += __shfl_xor_sync(FULLMASK, r[0], m);
        r[1] += __shfl_xor_sync(FULLMASK, r[1], m);
        r[2] += __shfl_xor_sync(FULLMASK, r[2], m);
        r[3] += __shfl_xor_sync(FULLMASK, r[3], m);
    }

    if (lane < 8) {
        float4 o4 = make_float4(r[0], r[1], r[2], r[3]);
        *reinterpret_cast<float4*>(out + (size_t)bq * 256 + h * 32 + lane * 4) = o4;
    }
}

extern "C" void kernel_launch(void* const* d_in, const int* in_sizes, int n_in,
                              void* d_out, int out_size)
{
    const float* value = (const float*)d_in[0];
    const float* loc   = (const float*)d_in[3];
    const float* attw  = (const float*)d_in[4];
    float* out = (float*)d_out;

    convert_kernel<<<10880, 256>>>(value);     // 87040 warps
    msda_kernel<<<87040, 256>>>(loc, attw, out);
}